// round 10
// baseline (speedup 1.0000x reference)
#include <cuda_runtime.h>

// Problem constants (fixed by the dataset)
#define NMAX 50000
#define EMAX 640000
#define GRP 8
#define PERM 1000003LL   // prime > any group-range -> bijective permutation
#define SCAN_CHUNK 1024
#define B_NODE 25088     // chunk split: 196*128, also divisible by 64

// Scratch (allocation-free rule: __device__ globals)
__device__ int   g_count[NMAX];
__device__ float g_dinv[NMAX];
__device__ int   g_part[256];
__device__ int   g_cursor[NMAX];
__device__ int   g_bound[1];            // offsets[B_NODE] snapshot
__device__ int4  g_pack[EMAX];          // {src, dst, norm_bits, 0}, dst-sorted
__device__ float g_h[NMAX * 128];
__device__ float g_agg1[NMAX * 128];
__device__ float g_agg2[NMAX * 128];
__device__ float g_h3[NMAX * 40];

__device__ __forceinline__ void red4(float* p, float a, float b, float c, float d) {
    asm volatile("red.global.add.v4.f32 [%0], {%1, %2, %3, %4};"
                 :: "l"(p), "f"(a), "f"(b), "f"(c), "f"(d) : "memory");
}

// ---------------------------------------------------------------------------
// Preamble
// ---------------------------------------------------------------------------
__global__ void zero_kernel(int* count, float* deg, int n) {
    int i = blockIdx.x * blockDim.x + threadIdx.x;
    if (i < n) { count[i] = 0; deg[i] = 1.0f; }
}

__global__ void hist_kernel(const int* __restrict__ dst,
                            const float* __restrict__ ew,
                            int* __restrict__ count,
                            float* __restrict__ deg, int e) {
    int i = blockIdx.x * blockDim.x + threadIdx.x;
    if (i < e) {
        int d = dst[i];
        atomicAdd(count + d, 1);
        atomicAdd(deg + d, ew[i]);
    }
}

__global__ void __launch_bounds__(256)
partial_kernel(const int* __restrict__ count, int* __restrict__ part, int n) {
    const int t = threadIdx.x;
    const int base = blockIdx.x * SCAN_CHUNK + t * 4;
    int s = 0;
#pragma unroll
    for (int i = 0; i < 4; i++) {
        int idx = base + i;
        if (idx < n) s += count[idx];
    }
#pragma unroll
    for (int o = 16; o; o >>= 1) s += __shfl_down_sync(~0u, s, o);
    __shared__ int wsum[8];
    if ((t & 31) == 0) wsum[t >> 5] = s;
    __syncthreads();
    if (t == 0) {
        int v = 0;
#pragma unroll
        for (int i = 0; i < 8; i++) v += wsum[i];
        part[blockIdx.x] = v;
    }
}

__global__ void __launch_bounds__(256)
scanpart_kernel(int* __restrict__ part, int nb) {
    __shared__ int sh[256];
    const int t = threadIdx.x;
    int orig = (t < nb) ? part[t] : 0;
    sh[t] = orig;
    __syncthreads();
    for (int off = 1; off < 256; off <<= 1) {
        int v = (t >= off) ? sh[t - off] : 0;
        __syncthreads();
        sh[t] += v;
        __syncthreads();
    }
    if (t < nb) part[t] = sh[t] - orig;
}

__global__ void __launch_bounds__(256)
scanfinal_kernel(const int* __restrict__ count,
                 const int* __restrict__ part,
                 float* __restrict__ deg_dinv,
                 int* __restrict__ cursor, int n) {
    const int t = threadIdx.x;
    const int base = blockIdx.x * SCAN_CHUNK + t * 4;
    int c[4];
    int s = 0;
#pragma unroll
    for (int i = 0; i < 4; i++) {
        int idx = base + i;
        c[i] = (idx < n) ? count[idx] : 0;
        s += c[i];
    }
    int inc = s;
#pragma unroll
    for (int o = 1; o < 32; o <<= 1) {
        int v = __shfl_up_sync(~0u, inc, o);
        if ((t & 31) >= o) inc += v;
    }
    __shared__ int wtot[8], woff[8];
    if ((t & 31) == 31) wtot[t >> 5] = inc;
    __syncthreads();
    if (t == 0) {
        int run = 0;
#pragma unroll
        for (int i = 0; i < 8; i++) { woff[i] = run; run += wtot[i]; }
    }
    __syncthreads();
    int run = inc - s + woff[t >> 5] + part[blockIdx.x];
#pragma unroll
    for (int i = 0; i < 4; i++) {
        int idx = base + i;
        if (idx < n) {
            cursor[idx] = run;
            run += c[i];
            deg_dinv[idx] = rsqrtf(deg_dinv[idx]);
        }
    }
}

// Snapshot offsets[B_NODE] before fill mutates cursor.
__global__ void grab_bound(const int* __restrict__ cursor, int* __restrict__ bound) {
    bound[0] = cursor[B_NODE];
}

__global__ void fill_kernel(const int* __restrict__ src,
                            const int* __restrict__ dst,
                            const float* __restrict__ ew,
                            const float* __restrict__ dinv,
                            int* __restrict__ cursor,
                            int4* __restrict__ pack, int e) {
    int i = blockIdx.x * blockDim.x + threadIdx.x;
    if (i >= e) return;
    int s = src[i];
    int d = dst[i];
    int pos = atomicAdd(cursor + d, 1);
    int4 p;
    p.x = s;
    p.y = d;
    p.z = __float_as_int(dinv[s] * ew[i] * dinv[d]);
    p.w = 0;
    pack[pos] = p;
}

// agg = h*dinv^2 + bias (layer-1 epilogue)
__global__ void agg_init128(const float* __restrict__ h,
                            const float* __restrict__ dinv,
                            const float* __restrict__ bias,
                            float* __restrict__ agg, int n) {
    int idx = blockIdx.x * blockDim.x + threadIdx.x;
    if (idx >= n * 32) return;
    int row = idx >> 5;
    int c = idx & 31;
    float di = dinv[row];
    di *= di;
    float4 hv = ((const float4*)h)[idx];
    float4 bv = ((const float4*)bias)[c];
    ((float4*)agg)[idx] = make_float4(fmaf(hv.x, di, bv.x), fmaf(hv.y, di, bv.y),
                                      fmaf(hv.z, di, bv.z), fmaf(hv.w, di, bv.w));
}

// ---------------------------------------------------------------------------
// GEMM: [n,128] @ [128,128], chunkable via block offset.
// ---------------------------------------------------------------------------
template <bool RELU_IN, bool FUSE_EPI>
__global__ void __launch_bounds__(256, 2)
gemm128_kernel(const float* __restrict__ A,
               const float* __restrict__ W,
               const float* __restrict__ bias,
               const float* __restrict__ dinv,
               float* __restrict__ Hout,
               float* __restrict__ AggOut,
               int n, int bOff) {
    __shared__ float As[16][128];
    __shared__ float Bs[16][128];

    const int tid = threadIdx.x;
    const int tx = tid & 15;
    const int ty = tid >> 4;
    const int rb = (blockIdx.x + bOff) * 128;

    float acc[8][8];
#pragma unroll
    for (int i = 0; i < 8; i++)
#pragma unroll
        for (int j = 0; j < 8; j++) acc[i][j] = 0.0f;

    for (int k0 = 0; k0 < 128; k0 += 16) {
#pragma unroll
        for (int l = 0; l < 2; l++) {
            int f = tid + l * 256;
            int row = f >> 2;
            int c4 = (f & 3) * 4;
            float4 v = make_float4(0.f, 0.f, 0.f, 0.f);
            int gr = rb + row;
            if (gr < n) v = *(const float4*)(A + (size_t)gr * 128 + k0 + c4);
            if (RELU_IN) {
                v.x = fmaxf(v.x, 0.f); v.y = fmaxf(v.y, 0.f);
                v.z = fmaxf(v.z, 0.f); v.w = fmaxf(v.w, 0.f);
            }
            As[c4 + 0][row] = v.x;
            As[c4 + 1][row] = v.y;
            As[c4 + 2][row] = v.z;
            As[c4 + 3][row] = v.w;
        }
#pragma unroll
        for (int l = 0; l < 2; l++) {
            int f = tid + l * 256;
            int kr = f >> 5;
            int c = (f & 31) * 4;
            *(float4*)&Bs[kr][c] = *(const float4*)(W + (size_t)(k0 + kr) * 128 + c);
        }
        __syncthreads();

#pragma unroll
        for (int k = 0; k < 16; k++) {
            float4 a0 = *(const float4*)&As[k][ty * 8];
            float4 a1 = *(const float4*)&As[k][ty * 8 + 4];
            float4 b0 = *(const float4*)&Bs[k][tx * 8];
            float4 b1 = *(const float4*)&Bs[k][tx * 8 + 4];
            float a[8] = {a0.x, a0.y, a0.z, a0.w, a1.x, a1.y, a1.z, a1.w};
            float b[8] = {b0.x, b0.y, b0.z, b0.w, b1.x, b1.y, b1.z, b1.w};
#pragma unroll
            for (int i = 0; i < 8; i++)
#pragma unroll
                for (int j = 0; j < 8; j++)
                    acc[i][j] = fmaf(a[i], b[j], acc[i][j]);
        }
        __syncthreads();
    }

#pragma unroll
    for (int i = 0; i < 8; i++) {
        int row = rb + ty * 8 + i;
        if (row >= n) break;
        float sl = 0.f;
        if (FUSE_EPI) { sl = dinv[row]; sl *= sl; }
#pragma unroll
        for (int j = 0; j < 8; j += 4) {
            int col = tx * 8 + j;
            float4 hv = make_float4(acc[i][j], acc[i][j + 1], acc[i][j + 2], acc[i][j + 3]);
            *(float4*)(Hout + (size_t)row * 128 + col) = hv;
            if (FUSE_EPI) {
                float4 bv = *(const float4*)(bias + col);
                float4 av;
                av.x = fmaf(hv.x, sl, bv.x);
                av.y = fmaf(hv.y, sl, bv.y);
                av.z = fmaf(hv.z, sl, bv.z);
                av.w = fmaf(hv.w, sl, bv.w);
                *(float4*)(AggOut + (size_t)row * 128 + col) = av;
            }
        }
    }
}

// ---------------------------------------------------------------------------
// Permuted segment-combining scatter (128 feats), chunked by group range.
// sel=0: groups [0, gb); sel=1: groups [gb, nw); gb = ceil(bound/GRP).
// ---------------------------------------------------------------------------
__global__ void __launch_bounds__(256)
scatter128_chunk(const float* __restrict__ h,
                 const int4* __restrict__ pack,
                 float* __restrict__ agg, int e, int nw,
                 const int* __restrict__ boundp, int sel) {
    int wl = (blockIdx.x * blockDim.x + threadIdx.x) >> 5;
    int lane = threadIdx.x & 31;
    int gb = (boundp[0] + GRP - 1) / GRP;
    int glo = sel ? gb : 0;
    int ghi = sel ? nw : gb;
    int range = ghi - glo;
    if (wl >= range) return;
    int w = glo + (int)(((long long)wl * PERM) % range);
    int base = w * GRP;
    int cnt = min(GRP, e - base);

    int4 p[GRP];
#pragma unroll
    for (int g = 0; g < GRP; g++)
        if (g < cnt) p[g] = pack[base + g];

    float4 m[GRP];
#pragma unroll
    for (int g = 0; g < GRP; g++)
        if (g < cnt)
            m[g] = *(const float4*)(h + (size_t)p[g].x * 128 + lane * 4);

#pragma unroll
    for (int g = 0; g < GRP; g++)
        if (g < cnt) {
            float nm = __int_as_float(p[g].z);
            m[g].x *= nm; m[g].y *= nm; m[g].z *= nm; m[g].w *= nm;
        }

    float4 acc = m[0];
    int d = p[0].y;
#pragma unroll
    for (int g = 1; g < GRP; g++) {
        if (g < cnt) {
            if (p[g].y == d) {
                acc.x += m[g].x; acc.y += m[g].y;
                acc.z += m[g].z; acc.w += m[g].w;
            } else {
                red4(agg + (size_t)d * 128 + lane * 4, acc.x, acc.y, acc.z, acc.w);
                acc = m[g];
                d = p[g].y;
            }
        }
    }
    red4(agg + (size_t)d * 128 + lane * 4, acc.x, acc.y, acc.z, acc.w);
}

// ---------------------------------------------------------------------------
// Layer-3 GEMM (chunkable): relu(A)[n,128] @ [128,40] -> H3 and Out init
// ---------------------------------------------------------------------------
__global__ void __launch_bounds__(128)
gemm40_kernel(const float* __restrict__ A,
              const float* __restrict__ W,
              const float* __restrict__ bias,
              const float* __restrict__ dinv,
              float* __restrict__ Hout,
              float* __restrict__ Out,
              int n, int bOff) {
    extern __shared__ float sm[];
    float* xs = sm;
    float* ws = sm + 64 * 129;

    const int tid = threadIdx.x;
    const int rb = (blockIdx.x + bOff) * 64;

    for (int l = tid * 4; l < 128 * 40; l += 128 * 4)
        *(float4*)(ws + l) = *(const float4*)(W + l);

    for (int f = tid; f < 2048; f += 128) {
        int row = f >> 5;
        int c = (f & 31) * 4;
        float4 v = make_float4(0.f, 0.f, 0.f, 0.f);
        int gr = rb + row;
        if (gr < n) v = *(const float4*)(A + (size_t)gr * 128 + c);
        float* xr = xs + row * 129 + c;
        xr[0] = fmaxf(v.x, 0.f);
        xr[1] = fmaxf(v.y, 0.f);
        xr[2] = fmaxf(v.z, 0.f);
        xr[3] = fmaxf(v.w, 0.f);
    }
    __syncthreads();

    const int tc = tid & 7;
    const int tr = tid >> 3;
    float acc[4][5];
#pragma unroll
    for (int r = 0; r < 4; r++)
#pragma unroll
        for (int j = 0; j < 5; j++) acc[r][j] = 0.0f;

#pragma unroll 4
    for (int k = 0; k < 128; k++) {
        float w[5];
#pragma unroll
        for (int j = 0; j < 5; j++) w[j] = ws[k * 40 + tc + 8 * j];
#pragma unroll
        for (int r = 0; r < 4; r++) {
            float a = xs[(tr * 4 + r) * 129 + k];
#pragma unroll
            for (int j = 0; j < 5; j++) acc[r][j] = fmaf(a, w[j], acc[r][j]);
        }
    }

#pragma unroll
    for (int r = 0; r < 4; r++) {
        int row = rb + tr * 4 + r;
        if (row >= n) break;
        float sl = dinv[row];
        sl = sl * sl;
#pragma unroll
        for (int j = 0; j < 5; j++) {
            int c = tc + 8 * j;
            float v = acc[r][j];
            Hout[(size_t)row * 40 + c] = v;
            Out[(size_t)row * 40 + c] = fmaf(v, sl, bias[c]);
        }
    }
}

// ---------------------------------------------------------------------------
// Permuted segment-combining scatter (40 feats), full range.
// ---------------------------------------------------------------------------
__global__ void __launch_bounds__(256)
scatter40_perm(const float* __restrict__ h,
               const int4* __restrict__ pack,
               float* __restrict__ out, int e, int nw) {
    int w = (blockIdx.x * blockDim.x + threadIdx.x) >> 5;
    int lane = threadIdx.x & 31;
    if (w >= nw) return;
    w = (int)(((long long)w * PERM) % nw);
    int base = w * GRP;
    int cnt = min(GRP, e - base);
    bool act = (lane < 10);

    int4 p[GRP];
#pragma unroll
    for (int g = 0; g < GRP; g++)
        if (g < cnt) p[g] = pack[base + g];

    float4 m[GRP];
#pragma unroll
    for (int g = 0; g < GRP; g++) {
        m[g] = make_float4(0.f, 0.f, 0.f, 0.f);
        if (g < cnt && act)
            m[g] = *(const float4*)(h + (size_t)p[g].x * 40 + lane * 4);
    }

#pragma unroll
    for (int g = 0; g < GRP; g++)
        if (g < cnt) {
            float nm = __int_as_float(p[g].z);
            m[g].x *= nm; m[g].y *= nm; m[g].z *= nm; m[g].w *= nm;
        }

    float4 acc = m[0];
    int d = p[0].y;
#pragma unroll
    for (int g = 1; g < GRP; g++) {
        if (g < cnt) {
            if (p[g].y == d) {
                acc.x += m[g].x; acc.y += m[g].y;
                acc.z += m[g].z; acc.w += m[g].w;
            } else {
                if (act)
                    red4(out + (size_t)d * 40 + lane * 4, acc.x, acc.y, acc.z, acc.w);
                acc = m[g];
                d = p[g].y;
            }
        }
    }
    if (act)
        red4(out + (size_t)d * 40 + lane * 4, acc.x, acc.y, acc.z, acc.w);
}

// ---------------------------------------------------------------------------
// Launch: gemm1 || preamble, then chunked scatter<->gemm pipeline.
// ---------------------------------------------------------------------------
extern "C" void kernel_launch(void* const* d_in, const int* in_sizes, int n_in,
                              void* d_out, int out_size) {
    const float* x  = (const float*)d_in[0];
    const int*   ei = (const int*)d_in[1];
    const float* ew = (const float*)d_in[2];
    const float* W1 = (const float*)d_in[3];
    const float* b1 = (const float*)d_in[4];
    const float* W2 = (const float*)d_in[5];
    const float* b2 = (const float*)d_in[6];
    const float* W3 = (const float*)d_in[7];
    const float* b3 = (const float*)d_in[8];
    float* out = (float*)d_out;

    const int n = in_sizes[0] / 128;       // 50000
    const int e = in_sizes[2];             // 640000
    const int* src = ei;
    const int* dst = ei + e;

    int *count, *cursor, *part, *bound;
    int4* pack;
    float *dinv, *h, *agg1, *agg2, *h3;
    cudaGetSymbolAddress((void**)&count,  g_count);
    cudaGetSymbolAddress((void**)&dinv,   g_dinv);
    cudaGetSymbolAddress((void**)&part,   g_part);
    cudaGetSymbolAddress((void**)&cursor, g_cursor);
    cudaGetSymbolAddress((void**)&bound,  g_bound);
    cudaGetSymbolAddress((void**)&pack,   g_pack);
    cudaGetSymbolAddress((void**)&h,      g_h);
    cudaGetSymbolAddress((void**)&agg1,   g_agg1);
    cudaGetSymbolAddress((void**)&agg2,   g_agg2);
    cudaGetSymbolAddress((void**)&h3,     g_h3);

    static cudaStream_t s2 = nullptr;
    static cudaEvent_t evFork, evG1, evS1A, evS1B, evG2B, evS2A, evS2B, evG40B;
    if (s2 == nullptr) {
        cudaStreamCreateWithFlags(&s2, cudaStreamNonBlocking);
        cudaEventCreateWithFlags(&evFork, cudaEventDisableTiming);
        cudaEventCreateWithFlags(&evG1, cudaEventDisableTiming);
        cudaEventCreateWithFlags(&evS1A, cudaEventDisableTiming);
        cudaEventCreateWithFlags(&evS1B, cudaEventDisableTiming);
        cudaEventCreateWithFlags(&evG2B, cudaEventDisableTiming);
        cudaEventCreateWithFlags(&evS2A, cudaEventDisableTiming);
        cudaEventCreateWithFlags(&evS2B, cudaEventDisableTiming);
        cudaEventCreateWithFlags(&evG40B, cudaEventDisableTiming);
    }

    const int nb_n = (n + 255) / 256;
    const int nb_e = (e + 255) / 256;
    const int nb_scan = (n + SCAN_CHUNK - 1) / SCAN_CHUNK;
    const int nw = (e + GRP - 1) / GRP;
    const int scat_blocks = (nw * 32 + 255) / 256;   // worst-case grid per chunk

    // gemm block counts per chunk
    const int g128_total = (n + 127) / 128;          // 391
    const int g128_A = B_NODE / 128;                 // 196
    const int g128_B = g128_total - g128_A;          // 195
    const int g40_total = (n + 63) / 64;             // 782
    const int g40_A = B_NODE / 64;                   // 392
    const int g40_B = g40_total - g40_A;             // 390

    static const int g40_smem = (64 * 129 + 128 * 40) * sizeof(float);
    cudaFuncSetAttribute(gemm40_kernel,
                         cudaFuncAttributeMaxDynamicSharedMemorySize, g40_smem);

    // Fork: gemm1 (graph-independent, H only) on s2
    cudaEventRecord(evFork, 0);
    cudaStreamWaitEvent(s2, evFork, 0);
    gemm128_kernel<false, false><<<g128_total, 256, 0, s2>>>(
        x, W1, nullptr, nullptr, h, nullptr, n, 0);
    cudaEventRecord(evG1, s2);

    // Preamble on main stream (concurrent with gemm1)
    zero_kernel<<<nb_n, 256>>>(count, dinv, n);
    hist_kernel<<<nb_e, 256>>>(dst, ew, count, dinv, e);
    partial_kernel<<<nb_scan, 256>>>(count, part, n);
    scanpart_kernel<<<1, 256>>>(part, nb_scan);
    scanfinal_kernel<<<nb_scan, 256>>>(count, part, dinv, cursor, n);
    grab_bound<<<1, 1>>>(cursor, bound);
    fill_kernel<<<nb_e, 256>>>(src, dst, ew, dinv, cursor, pack, e);

    // Join; layer-1 epilogue
    cudaStreamWaitEvent(0, evG1, 0);
    agg_init128<<<(n * 32 + 255) / 256, 256>>>(h, dinv, b1, agg1, n);

    // ---- Pipelined layers ----
    // scat1A -> (scat1B || gemm2A) -> gemm2B -> scat2A -> (scat2B || gemm40A)
    // -> gemm40B -> scat40
    scatter128_chunk<<<scat_blocks, 256>>>(h, pack, agg1, e, nw, bound, 0);
    cudaEventRecord(evS1A, 0);

    cudaStreamWaitEvent(s2, evS1A, 0);
    gemm128_kernel<true, true><<<g128_A, 256, 0, s2>>>(
        agg1, W2, b2, dinv, h, agg2, n, 0);

    scatter128_chunk<<<scat_blocks, 256>>>(h, pack, agg1, e, nw, bound, 1);
    cudaEventRecord(evS1B, 0);

    cudaStreamWaitEvent(s2, evS1B, 0);
    gemm128_kernel<true, true><<<g128_B, 256, 0, s2>>>(
        agg1, W2, b2, dinv, h, agg2, n, g128_A);
    cudaEventRecord(evG2B, s2);

    cudaStreamWaitEvent(0, evG2B, 0);   // scat2 needs FULL h (random srcs)
    scatter128_chunk<<<scat_blocks, 256>>>(h, pack, agg2, e, nw, bound, 0);
    cudaEventRecord(evS2A, 0);

    cudaStreamWaitEvent(s2, evS2A, 0);
    gemm40_kernel<<<g40_A, 128, g40_smem, s2>>>(agg2, W3, b3, dinv, h3, out, n, 0);

    scatter128_chunk<<<scat_blocks, 256>>>(h, pack, agg2, e, nw, bound, 1);
    cudaEventRecord(evS2B, 0);

    cudaStreamWaitEvent(s2, evS2B, 0);
    gemm40_kernel<<<g40_B, 128, g40_smem, s2>>>(agg2, W3, b3, dinv, h3, out, n, g40_A);
    cudaEventRecord(evG40B, s2);

    cudaStreamWaitEvent(0, evG40B, 0);  // scat40 needs FULL h3
    scatter40_perm<<<scat_blocks, 256>>>(h3, pack, out, e, nw);
}

// round 11
// speedup vs baseline: 1.0775x; 1.0775x over previous
#include <cuda_runtime.h>
#include <cuda_fp16.h>

// Problem constants (fixed by the dataset)
#define NMAX 50000
#define EMAX 640000
#define GRP 8
#define PERM 1000003LL   // prime > group count -> bijective permutation
#define SCAN_CHUNK 1024

// Scratch (allocation-free rule: __device__ globals)
__device__ int    g_count[NMAX];
__device__ float  g_dinv[NMAX];
__device__ int    g_part[256];
__device__ int    g_cursor[NMAX];
__device__ int4   g_pack[EMAX];          // {src, dst, norm_bits, 0}, dst-sorted
__device__ __half g_h[NMAX * 128];       // GEMM output, fp16 (gather path)
__device__ float  g_agg1[NMAX * 128];    // layer-1 aggregation (fp32)
__device__ float  g_agg2[NMAX * 128];    // layer-2 aggregation (fp32)
__device__ __half g_h3[NMAX * 40];       // layer-3 GEMM output, fp16

__device__ __forceinline__ void red4(float* p, float a, float b, float c, float d) {
    asm volatile("red.global.add.v4.f32 [%0], {%1, %2, %3, %4};"
                 :: "l"(p), "f"(a), "f"(b), "f"(c), "f"(d) : "memory");
}

// Load 4 consecutive fp16 (8B) and widen to float4.
__device__ __forceinline__ float4 ld_half4(const __half* p) {
    uint2 u = *(const uint2*)p;
    __half2 h0 = *(__half2*)&u.x;
    __half2 h1 = *(__half2*)&u.y;
    float2 f0 = __half22float2(h0);
    float2 f1 = __half22float2(h1);
    return make_float4(f0.x, f0.y, f1.x, f1.y);
}

// ---------------------------------------------------------------------------
// Preamble
// ---------------------------------------------------------------------------
__global__ void zero_kernel(int* count, float* deg, int n) {
    int i = blockIdx.x * blockDim.x + threadIdx.x;
    if (i < n) { count[i] = 0; deg[i] = 1.0f; }
}

__global__ void hist_kernel(const int* __restrict__ dst,
                            const float* __restrict__ ew,
                            int* __restrict__ count,
                            float* __restrict__ deg, int e) {
    int i = blockIdx.x * blockDim.x + threadIdx.x;
    if (i < e) {
        int d = dst[i];
        atomicAdd(count + d, 1);
        atomicAdd(deg + d, ew[i]);
    }
}

__global__ void __launch_bounds__(256)
partial_kernel(const int* __restrict__ count, int* __restrict__ part, int n) {
    const int t = threadIdx.x;
    const int base = blockIdx.x * SCAN_CHUNK + t * 4;
    int s = 0;
#pragma unroll
    for (int i = 0; i < 4; i++) {
        int idx = base + i;
        if (idx < n) s += count[idx];
    }
#pragma unroll
    for (int o = 16; o; o >>= 1) s += __shfl_down_sync(~0u, s, o);
    __shared__ int wsum[8];
    if ((t & 31) == 0) wsum[t >> 5] = s;
    __syncthreads();
    if (t == 0) {
        int v = 0;
#pragma unroll
        for (int i = 0; i < 8; i++) v += wsum[i];
        part[blockIdx.x] = v;
    }
}

__global__ void __launch_bounds__(256)
scanpart_kernel(int* __restrict__ part, int nb) {
    __shared__ int sh[256];
    const int t = threadIdx.x;
    int orig = (t < nb) ? part[t] : 0;
    sh[t] = orig;
    __syncthreads();
    for (int off = 1; off < 256; off <<= 1) {
        int v = (t >= off) ? sh[t - off] : 0;
        __syncthreads();
        sh[t] += v;
        __syncthreads();
    }
    if (t < nb) part[t] = sh[t] - orig;
}

__global__ void __launch_bounds__(256)
scanfinal_kernel(const int* __restrict__ count,
                 const int* __restrict__ part,
                 float* __restrict__ deg_dinv,
                 int* __restrict__ cursor, int n) {
    const int t = threadIdx.x;
    const int base = blockIdx.x * SCAN_CHUNK + t * 4;
    int c[4];
    int s = 0;
#pragma unroll
    for (int i = 0; i < 4; i++) {
        int idx = base + i;
        c[i] = (idx < n) ? count[idx] : 0;
        s += c[i];
    }
    int inc = s;
#pragma unroll
    for (int o = 1; o < 32; o <<= 1) {
        int v = __shfl_up_sync(~0u, inc, o);
        if ((t & 31) >= o) inc += v;
    }
    __shared__ int wtot[8], woff[8];
    if ((t & 31) == 31) wtot[t >> 5] = inc;
    __syncthreads();
    if (t == 0) {
        int run = 0;
#pragma unroll
        for (int i = 0; i < 8; i++) { woff[i] = run; run += wtot[i]; }
    }
    __syncthreads();
    int run = inc - s + woff[t >> 5] + part[blockIdx.x];
#pragma unroll
    for (int i = 0; i < 4; i++) {
        int idx = base + i;
        if (idx < n) {
            cursor[idx] = run;
            run += c[i];
            deg_dinv[idx] = rsqrtf(deg_dinv[idx]);
        }
    }
}

__global__ void fill_kernel(const int* __restrict__ src,
                            const int* __restrict__ dst,
                            const float* __restrict__ ew,
                            const float* __restrict__ dinv,
                            int* __restrict__ cursor,
                            int4* __restrict__ pack, int e) {
    int i = blockIdx.x * blockDim.x + threadIdx.x;
    if (i >= e) return;
    int s = src[i];
    int d = dst[i];
    int pos = atomicAdd(cursor + d, 1);
    int4 p;
    p.x = s;
    p.y = d;
    p.z = __float_as_int(dinv[s] * ew[i] * dinv[d]);
    p.w = 0;
    pack[pos] = p;
}

// agg = h*dinv^2 + bias (layer-1 epilogue; h is fp16)
__global__ void agg_init128(const __half* __restrict__ h,
                            const float* __restrict__ dinv,
                            const float* __restrict__ bias,
                            float* __restrict__ agg, int n) {
    int idx = blockIdx.x * blockDim.x + threadIdx.x;   // 4-col chunk index
    if (idx >= n * 32) return;
    int row = idx >> 5;
    int c = idx & 31;
    float di = dinv[row];
    di *= di;
    float4 hv = ld_half4(h + (size_t)row * 128 + c * 4);
    float4 bv = ((const float4*)bias)[c];
    ((float4*)agg)[idx] = make_float4(fmaf(hv.x, di, bv.x), fmaf(hv.y, di, bv.y),
                                      fmaf(hv.z, di, bv.z), fmaf(hv.w, di, bv.w));
}

// ---------------------------------------------------------------------------
// GEMM: [n,128] @ [128,128]. H written as fp16; Agg (if fused) from fp32 acc.
// ---------------------------------------------------------------------------
template <bool RELU_IN, bool FUSE_EPI>
__global__ void __launch_bounds__(256, 2)
gemm128_kernel(const float* __restrict__ A,
               const float* __restrict__ W,
               const float* __restrict__ bias,
               const float* __restrict__ dinv,
               __half* __restrict__ Hout,
               float* __restrict__ AggOut,
               int n) {
    __shared__ float As[16][128];
    __shared__ float Bs[16][128];

    const int tid = threadIdx.x;
    const int tx = tid & 15;
    const int ty = tid >> 4;
    const int rb = blockIdx.x * 128;

    float acc[8][8];
#pragma unroll
    for (int i = 0; i < 8; i++)
#pragma unroll
        for (int j = 0; j < 8; j++) acc[i][j] = 0.0f;

    for (int k0 = 0; k0 < 128; k0 += 16) {
#pragma unroll
        for (int l = 0; l < 2; l++) {
            int f = tid + l * 256;
            int row = f >> 2;
            int c4 = (f & 3) * 4;
            float4 v = make_float4(0.f, 0.f, 0.f, 0.f);
            int gr = rb + row;
            if (gr < n) v = *(const float4*)(A + (size_t)gr * 128 + k0 + c4);
            if (RELU_IN) {
                v.x = fmaxf(v.x, 0.f); v.y = fmaxf(v.y, 0.f);
                v.z = fmaxf(v.z, 0.f); v.w = fmaxf(v.w, 0.f);
            }
            As[c4 + 0][row] = v.x;
            As[c4 + 1][row] = v.y;
            As[c4 + 2][row] = v.z;
            As[c4 + 3][row] = v.w;
        }
#pragma unroll
        for (int l = 0; l < 2; l++) {
            int f = tid + l * 256;
            int kr = f >> 5;
            int c = (f & 31) * 4;
            *(float4*)&Bs[kr][c] = *(const float4*)(W + (size_t)(k0 + kr) * 128 + c);
        }
        __syncthreads();

#pragma unroll
        for (int k = 0; k < 16; k++) {
            float4 a0 = *(const float4*)&As[k][ty * 8];
            float4 a1 = *(const float4*)&As[k][ty * 8 + 4];
            float4 b0 = *(const float4*)&Bs[k][tx * 8];
            float4 b1 = *(const float4*)&Bs[k][tx * 8 + 4];
            float a[8] = {a0.x, a0.y, a0.z, a0.w, a1.x, a1.y, a1.z, a1.w};
            float b[8] = {b0.x, b0.y, b0.z, b0.w, b1.x, b1.y, b1.z, b1.w};
#pragma unroll
            for (int i = 0; i < 8; i++)
#pragma unroll
                for (int j = 0; j < 8; j++)
                    acc[i][j] = fmaf(a[i], b[j], acc[i][j]);
        }
        __syncthreads();
    }

#pragma unroll
    for (int i = 0; i < 8; i++) {
        int row = rb + ty * 8 + i;
        if (row >= n) break;
        float sl = 0.f;
        if (FUSE_EPI) { sl = dinv[row]; sl *= sl; }
        // pack 8 fp16 (16B) for this row
        __half2 hp[4];
#pragma unroll
        for (int j = 0; j < 4; j++)
            hp[j] = __floats2half2_rn(acc[i][j * 2], acc[i][j * 2 + 1]);
        *(uint4*)(Hout + (size_t)row * 128 + tx * 8) = *(uint4*)hp;

        if (FUSE_EPI) {
#pragma unroll
            for (int j = 0; j < 8; j += 4) {
                int col = tx * 8 + j;
                float4 bv = *(const float4*)(bias + col);
                float4 av;
                av.x = fmaf(acc[i][j + 0], sl, bv.x);
                av.y = fmaf(acc[i][j + 1], sl, bv.y);
                av.z = fmaf(acc[i][j + 2], sl, bv.z);
                av.w = fmaf(acc[i][j + 3], sl, bv.w);
                *(float4*)(AggOut + (size_t)row * 128 + col) = av;
            }
        }
    }
}

// ---------------------------------------------------------------------------
// Permuted segment-combining scatter (128 feats), fp16 gather.
// ---------------------------------------------------------------------------
__global__ void __launch_bounds__(256)
scatter128_perm(const __half* __restrict__ h,
                const int4* __restrict__ pack,
                float* __restrict__ agg, int e, int nw) {
    int w = (blockIdx.x * blockDim.x + threadIdx.x) >> 5;
    int lane = threadIdx.x & 31;
    if (w >= nw) return;
    w = (int)(((long long)w * PERM) % nw);   // decorrelate concurrent dsts
    int base = w * GRP;
    int cnt = min(GRP, e - base);

    int4 p[GRP];
#pragma unroll
    for (int g = 0; g < GRP; g++)
        if (g < cnt) p[g] = pack[base + g];

    float4 m[GRP];
#pragma unroll
    for (int g = 0; g < GRP; g++)
        if (g < cnt)
            m[g] = ld_half4(h + (size_t)p[g].x * 128 + lane * 4);

#pragma unroll
    for (int g = 0; g < GRP; g++)
        if (g < cnt) {
            float nm = __int_as_float(p[g].z);
            m[g].x *= nm; m[g].y *= nm; m[g].z *= nm; m[g].w *= nm;
        }

    float4 acc = m[0];
    int d = p[0].y;
#pragma unroll
    for (int g = 1; g < GRP; g++) {
        if (g < cnt) {
            if (p[g].y == d) {                 // warp-uniform branch
                acc.x += m[g].x; acc.y += m[g].y;
                acc.z += m[g].z; acc.w += m[g].w;
            } else {
                red4(agg + (size_t)d * 128 + lane * 4, acc.x, acc.y, acc.z, acc.w);
                acc = m[g];
                d = p[g].y;
            }
        }
    }
    red4(agg + (size_t)d * 128 + lane * 4, acc.x, acc.y, acc.z, acc.w);
}

// ---------------------------------------------------------------------------
// Layer-3 GEMM: relu(A)[n,128] @ [128,40] -> H3 (fp16) and Out init (fp32)
// ---------------------------------------------------------------------------
__global__ void __launch_bounds__(128)
gemm40_kernel(const float* __restrict__ A,
              const float* __restrict__ W,
              const float* __restrict__ bias,
              const float* __restrict__ dinv,
              __half* __restrict__ Hout,
              float* __restrict__ Out,
              int n) {
    extern __shared__ float sm[];
    float* xs = sm;                 // 64 rows, stride 129
    float* ws = sm + 64 * 129;      // 128*40 flat

    const int tid = threadIdx.x;
    const int rb = blockIdx.x * 64;

    for (int l = tid * 4; l < 128 * 40; l += 128 * 4)
        *(float4*)(ws + l) = *(const float4*)(W + l);

    for (int f = tid; f < 2048; f += 128) {
        int row = f >> 5;
        int c = (f & 31) * 4;
        float4 v = make_float4(0.f, 0.f, 0.f, 0.f);
        int gr = rb + row;
        if (gr < n) v = *(const float4*)(A + (size_t)gr * 128 + c);
        float* xr = xs + row * 129 + c;
        xr[0] = fmaxf(v.x, 0.f);
        xr[1] = fmaxf(v.y, 0.f);
        xr[2] = fmaxf(v.z, 0.f);
        xr[3] = fmaxf(v.w, 0.f);
    }
    __syncthreads();

    const int tc = tid & 7;
    const int tr = tid >> 3;
    float acc[4][5];
#pragma unroll
    for (int r = 0; r < 4; r++)
#pragma unroll
        for (int j = 0; j < 5; j++) acc[r][j] = 0.0f;

#pragma unroll 4
    for (int k = 0; k < 128; k++) {
        float w[5];
#pragma unroll
        for (int j = 0; j < 5; j++) w[j] = ws[k * 40 + tc + 8 * j];
#pragma unroll
        for (int r = 0; r < 4; r++) {
            float a = xs[(tr * 4 + r) * 129 + k];
#pragma unroll
            for (int j = 0; j < 5; j++) acc[r][j] = fmaf(a, w[j], acc[r][j]);
        }
    }

#pragma unroll
    for (int r = 0; r < 4; r++) {
        int row = rb + tr * 4 + r;
        if (row >= n) break;
        float sl = dinv[row];
        sl = sl * sl;
#pragma unroll
        for (int j = 0; j < 5; j++) {
            int c = tc + 8 * j;
            float v = acc[r][j];
            Hout[(size_t)row * 40 + c] = __float2half_rn(v);
            Out[(size_t)row * 40 + c] = fmaf(v, sl, bias[c]);
        }
    }
}

// ---------------------------------------------------------------------------
// Permuted segment-combining scatter (40 feats), fp16 gather; lanes 0..9.
// ---------------------------------------------------------------------------
__global__ void __launch_bounds__(256)
scatter40_perm(const __half* __restrict__ h,
               const int4* __restrict__ pack,
               float* __restrict__ out, int e, int nw) {
    int w = (blockIdx.x * blockDim.x + threadIdx.x) >> 5;
    int lane = threadIdx.x & 31;
    if (w >= nw) return;
    w = (int)(((long long)w * PERM) % nw);
    int base = w * GRP;
    int cnt = min(GRP, e - base);
    bool act = (lane < 10);

    int4 p[GRP];
#pragma unroll
    for (int g = 0; g < GRP; g++)
        if (g < cnt) p[g] = pack[base + g];

    float4 m[GRP];
#pragma unroll
    for (int g = 0; g < GRP; g++) {
        m[g] = make_float4(0.f, 0.f, 0.f, 0.f);
        if (g < cnt && act)
            m[g] = ld_half4(h + (size_t)p[g].x * 40 + lane * 4);
    }

#pragma unroll
    for (int g = 0; g < GRP; g++)
        if (g < cnt) {
            float nm = __int_as_float(p[g].z);
            m[g].x *= nm; m[g].y *= nm; m[g].z *= nm; m[g].w *= nm;
        }

    float4 acc = m[0];
    int d = p[0].y;
#pragma unroll
    for (int g = 1; g < GRP; g++) {
        if (g < cnt) {
            if (p[g].y == d) {
                acc.x += m[g].x; acc.y += m[g].y;
                acc.z += m[g].z; acc.w += m[g].w;
            } else {
                if (act)
                    red4(out + (size_t)d * 40 + lane * 4, acc.x, acc.y, acc.z, acc.w);
                acc = m[g];
                d = p[g].y;
            }
        }
    }
    if (act)
        red4(out + (size_t)d * 40 + lane * 4, acc.x, acc.y, acc.z, acc.w);
}

// ---------------------------------------------------------------------------
// Launch: gemm1 overlaps the graph preamble on a second stream (round-9 shape).
// ---------------------------------------------------------------------------
extern "C" void kernel_launch(void* const* d_in, const int* in_sizes, int n_in,
                              void* d_out, int out_size) {
    const float* x  = (const float*)d_in[0];
    const int*   ei = (const int*)d_in[1];
    const float* ew = (const float*)d_in[2];
    const float* W1 = (const float*)d_in[3];
    const float* b1 = (const float*)d_in[4];
    const float* W2 = (const float*)d_in[5];
    const float* b2 = (const float*)d_in[6];
    const float* W3 = (const float*)d_in[7];
    const float* b3 = (const float*)d_in[8];
    float* out = (float*)d_out;

    const int n = in_sizes[0] / 128;       // 50000
    const int e = in_sizes[2];             // 640000
    const int* src = ei;
    const int* dst = ei + e;

    int *count, *cursor, *part;
    int4* pack;
    float *dinv, *agg1, *agg2;
    __half *h, *h3;
    cudaGetSymbolAddress((void**)&count,  g_count);
    cudaGetSymbolAddress((void**)&dinv,   g_dinv);
    cudaGetSymbolAddress((void**)&part,   g_part);
    cudaGetSymbolAddress((void**)&cursor, g_cursor);
    cudaGetSymbolAddress((void**)&pack,   g_pack);
    cudaGetSymbolAddress((void**)&h,      g_h);
    cudaGetSymbolAddress((void**)&agg1,   g_agg1);
    cudaGetSymbolAddress((void**)&agg2,   g_agg2);
    cudaGetSymbolAddress((void**)&h3,     g_h3);

    static cudaStream_t s2 = nullptr;
    static cudaEvent_t evFork = nullptr, evG1 = nullptr;
    if (s2 == nullptr) {
        cudaStreamCreateWithFlags(&s2, cudaStreamNonBlocking);
        cudaEventCreateWithFlags(&evFork, cudaEventDisableTiming);
        cudaEventCreateWithFlags(&evG1, cudaEventDisableTiming);
    }

    const int nb_n = (n + 255) / 256;
    const int nb_e = (e + 255) / 256;
    const int nb_scan = (n + SCAN_CHUNK - 1) / SCAN_CHUNK;   // 49
    const int gemm_blocks = (n + 127) / 128;
    const int nw = (e + GRP - 1) / GRP;
    const int scat_blocks = (nw * 32 + 255) / 256;

    // Fork: gemm1 (graph-independent, H only) on s2
    cudaEventRecord(evFork, 0);
    cudaStreamWaitEvent(s2, evFork, 0);
    gemm128_kernel<false, false><<<gemm_blocks, 256, 0, s2>>>(
        x, W1, nullptr, nullptr, h, nullptr, n);
    cudaEventRecord(evG1, s2);

    // Preamble on main stream (concurrent with gemm1)
    zero_kernel<<<nb_n, 256>>>(count, dinv, n);
    hist_kernel<<<nb_e, 256>>>(dst, ew, count, dinv, e);
    partial_kernel<<<nb_scan, 256>>>(count, part, n);
    scanpart_kernel<<<1, 256>>>(part, nb_scan);
    scanfinal_kernel<<<nb_scan, 256>>>(count, part, dinv, cursor, n);
    fill_kernel<<<nb_e, 256>>>(src, dst, ew, dinv, cursor, pack, e);

    // Join, then layer-1 epilogue + scatter
    cudaStreamWaitEvent(0, evG1, 0);
    agg_init128<<<(n * 32 + 255) / 256, 256>>>(h, dinv, b1, agg1, n);
    scatter128_perm<<<scat_blocks, 256>>>(h, pack, agg1, e, nw);

    // Layer 2 (relu + fused epilogue)
    gemm128_kernel<true, true><<<gemm_blocks, 256>>>(agg1, W2, b2, dinv, h, agg2, n);
    scatter128_perm<<<scat_blocks, 256>>>(h, pack, agg2, e, nw);

    // Layer 3 (relu fused; scatter straight to d_out)
    static const int g40_smem = (64 * 129 + 128 * 40) * sizeof(float);
    cudaFuncSetAttribute(gemm40_kernel,
                         cudaFuncAttributeMaxDynamicSharedMemorySize, g40_smem);
    gemm40_kernel<<<(n + 63) / 64, 128, g40_smem>>>(agg2, W3, b3, dinv, h3, out, n);
    scatter40_perm<<<scat_blocks, 256>>>(h3, pack, out, e, nw);
}